// round 10
// baseline (speedup 1.0000x reference)
#include <cuda_runtime.h>
#include <cstdint>

typedef unsigned long long u64;
typedef unsigned int u32;

#define TOKENS   2048
#define IN_DIM   1024
#define OUT_DIM  512
#define RANK     32
#define NTG      32
#define NTILE    16
#define TILE_TOK 128
#define OC       32              // outputs per block (occupancy: 2 blocks/SM)
#define MAXIT    640
#define MAXRD    20              // max rounds (MAXIT/32)
#define WROW     36              // floats per weight row (32 + 4 pad)
#define WCELL    (33*WROW)       // 1188 floats per cell (32 w rows + bias row)
#define WBUF     (4*WCELL)       // 4752 floats per tg buffer (19008 B)
#define ZROW     136             // 128 tokens + 8 dummy cols (u64 entries)
#define ACCS     36              // acc row stride (floats)

// ---------------- scratch (static device globals: allocation-free) ----------
__device__ __align__(16) float         g_z[TOKENS * RANK];
__device__ __align__(16) unsigned char g_win[TOKENS * NTG];
__device__ __align__(16) u64           g_itok[NTILE * MAXIT];
__device__ u32                         g_imeta[NTILE * MAXIT];
__device__ u32                         g_rdesc[NTILE * MAXRD];
__device__ int                         g_nit[NTILE];
__device__ int                         g_dummy;

// ---------------- helpers ----------------------------------------------------
__device__ __forceinline__ u64 dup2(float v) {
    u64 r; asm("mov.b64 %0, {%1, %1};" : "=l"(r) : "f"(v)); return r;
}
__device__ __forceinline__ void ffma2(u64& d, u64 a, u64 b) {
    asm("fma.rn.f32x2 %0, %1, %2, %0;" : "+l"(d) : "l"(a), "l"(b));
}

// =============================================================================
// Kernel 0: profiler-alignment dummy (ncu captures launch #4 = kApply).
// =============================================================================
__global__ void kInit() { if (threadIdx.x == 0) g_dummy = 1; }

// =============================================================================
// Kernel 1: z projection + routing argmin.  (verified 12.6us)
// =============================================================================
#define SMEM_ROUTE 50816

__global__ __launch_bounds__(256) void kRoute(
    const float* __restrict__ x, const float* __restrict__ proj_w,
    const float* __restrict__ router_w, const float* __restrict__ router_b) {
    extern __shared__ __align__(16) unsigned char smr[];
    float* xs   = (float*)smr;                       // [8][1024]
    float* rw_s = (float*)(smr + 32768);             // [32][129]
    float* rb_s = (float*)(smr + 49280);             // [128]
    float* zs   = (float*)(smr + 49792);             // [8][32]

    const int tid  = threadIdx.x;
    const int tok0 = blockIdx.x * 8;

    {   // stage 8 token rows of x (coalesced float4)
        const float4* xg  = (const float4*)(x + (size_t)tok0 * IN_DIM);
        float4*       xs4 = (float4*)xs;
#pragma unroll
        for (int i = 0; i < 8; i++) xs4[tid + 256 * i] = xg[tid + 256 * i];
    }
    {   // stage router_w coalesced -> padded rows (stride 129, bank-safe)
#pragma unroll
        for (int e = tid; e < 1024; e += 256) {
            const float4 v = ((const float4*)router_w)[e];
            const int tg = e >> 5, w4 = e & 31;
            float* d = &rw_s[tg * 129 + (w4 >> 3) * 32 + (w4 & 7) * 4];
            d[0] = v.x; d[1] = v.y; d[2] = v.z; d[3] = v.w;
        }
        if (tid < 128) rb_s[tid] = router_b[tid];
    }
    __syncthreads();

    const int w = tid >> 5, lane = tid & 31;
    float acc[4][8];
#pragma unroll
    for (int j = 0; j < 4; j++)
#pragma unroll
        for (int t = 0; t < 8; t++) acc[j][t] = 0.f;

    const float4* pw4 = (const float4*)(proj_w + (size_t)(w * 4) * IN_DIM) + lane;
    const float4* xs4 = (const float4*)xs + lane;

    float4 wv[4], wn[4];
#pragma unroll
    for (int j = 0; j < 4; j++) wv[j] = __ldg(pw4 + j * 256);

#pragma unroll
    for (int ci = 0; ci < 8; ci++) {
        if (ci < 7)
#pragma unroll
            for (int j = 0; j < 4; j++)
                wn[j] = __ldg(pw4 + j * 256 + (ci + 1) * 32);
#pragma unroll
        for (int t = 0; t < 8; t++) {
            const float4 xv = xs4[t * 256 + ci * 32];
#pragma unroll
            for (int j = 0; j < 4; j++) {
                acc[j][t] += wv[j].x * xv.x;
                acc[j][t] += wv[j].y * xv.y;
                acc[j][t] += wv[j].z * xv.z;
                acc[j][t] += wv[j].w * xv.w;
            }
        }
#pragma unroll
        for (int j = 0; j < 4; j++) wv[j] = wn[j];
    }

#pragma unroll
    for (int j = 0; j < 4; j++)
#pragma unroll
        for (int t = 0; t < 8; t++) {
            float s = acc[j][t];
#pragma unroll
            for (int off = 16; off > 0; off >>= 1)
                s += __shfl_xor_sync(0xffffffffu, s, off);
            if (lane == 0) zs[t * 32 + w * 4 + j] = s;
        }
    __syncthreads();

    if (tid < 64)
        ((float4*)(g_z + (size_t)tok0 * RANK))[tid] = ((const float4*)zs)[tid];

    {
        const int t  = tid >> 5;
        const int tg = tid & 31;
        float s[4];
#pragma unroll
        for (int k = 0; k < 4; k++) s[k] = rb_s[tg * 4 + k];
#pragma unroll 8
        for (int r = 0; r < RANK; r++) {
            const float zr = zs[t * 32 + r];
#pragma unroll
            for (int k = 0; k < 4; k++) s[k] += zr * rw_s[tg * 129 + k * 32 + r];
        }
        int best = 0; float bv = s[0];
#pragma unroll
        for (int k = 1; k < 4; k++)
            if (s[k] < bv) { bv = s[k]; best = k; }
        g_win[(size_t)(tok0 + t) * NTG + tg] = (unsigned char)best;
    }
}

// =============================================================================
// Kernel 2: per-tile cell sort -> flat item list (tg-ordered) + round descs.
// =============================================================================
__global__ __launch_bounds__(128) void kSort() {
    __shared__ unsigned char win_t[NTG][132];
    __shared__ unsigned char ord[NTG][160];
    __shared__ unsigned char offp[NTG][5];
    __shared__ int it_cnt[NTG];
    __shared__ int it_off[NTG + 1];
    __shared__ u64 s_itok[MAXIT];
    __shared__ u32 s_imeta[MAXIT];

    const int tid   = threadIdx.x;
    const int tile0 = blockIdx.x * TILE_TOK;

    {   // transpose win: [tok][tg] -> win_t[tg][tok]
        const u32* wp = (const u32*)(g_win + (size_t)(tile0 + tid) * NTG);
#pragma unroll
        for (int q = 0; q < 8; q++) {
            const u32 v = wp[q];
            win_t[q * 4 + 0][tid] = (unsigned char)(v);
            win_t[q * 4 + 1][tid] = (unsigned char)(v >> 8);
            win_t[q * 4 + 2][tid] = (unsigned char)(v >> 16);
            win_t[q * 4 + 3][tid] = (unsigned char)(v >> 24);
        }
    }
    __syncthreads();

    if (tid < NTG) {
        const int tg = tid;
        int cnt[4] = {0, 0, 0, 0};
        for (int t = 0; t < TILE_TOK; t++) cnt[win_t[tg][t]]++;
        int o[5]; o[0] = 0;
#pragma unroll
        for (int c = 0; c < 4; c++) o[c + 1] = o[c] + ((cnt[c] + 7) & ~7);
        int pos[4];
#pragma unroll
        for (int c = 0; c < 4; c++) pos[c] = o[c];
        for (int t = 0; t < TILE_TOK; t++) {
            const int c = win_t[tg][t];
            ord[tg][pos[c]++] = (unsigned char)t;
        }
#pragma unroll
        for (int c = 0; c < 4; c++)
            for (int i = cnt[c]; i < ((cnt[c] + 7) & ~7); i++)
                ord[tg][o[c] + i] = 128;               // dummy token
        it_cnt[tg] = o[4] >> 3;
#pragma unroll
        for (int c = 0; c < 5; c++) offp[tg][c] = (unsigned char)o[c];
    }
    __syncthreads();

    if (tid == 0) {
        int run = 0;
        for (int tg = 0; tg < NTG; tg++) { it_off[tg] = run; run += it_cnt[tg]; }
        it_off[NTG] = run;
    }
    __syncthreads();

    if (tid < NTG) {
        const int tg   = tid;
        const int base = it_off[tg];
        const int n    = it_cnt[tg];
        for (int i = 0; i < n; i++) {
            const int slot = i * 8;
            int cell = 3;
#pragma unroll
            for (int c = 0; c < 3; c++)
                if (slot < (int)offp[tg][c + 1]) { cell = c; break; }
            u64 tk = 0;
#pragma unroll
            for (int j = 0; j < 8; j++)
                tk |= (u64)ord[tg][slot + j] << (8 * j);
            s_itok[base + i]  = tk;
            s_imeta[base + i] = (u32)cell | ((u32)tg << 8);
        }
    }
    __syncthreads();

    const int total  = it_off[NTG];
    const int padded = (total + 31) & ~31;             // 32-item rounds
    if (tid == 0) g_nit[blockIdx.x] = padded;
    for (int e = total + tid; e < padded; e += 128) {
        s_itok[e]  = 0x8080808080808080ull;            // all-dummy item
        s_imeta[e] = (31u << 8);                       // tg 31, cell 0
    }
    __syncthreads();
    for (int e = tid; e < padded; e += 128) {
        g_itok[blockIdx.x * MAXIT + e]  = s_itok[e];
        g_imeta[blockIdx.x * MAXIT + e] = s_imeta[e];
    }
    const int nrounds = padded >> 5;
    if (tid < nrounds) {
        const u32 ft = s_imeta[tid * 32] >> 8;
        const u32 lt = s_imeta[tid * 32 + 31] >> 8;
        g_rdesc[blockIdx.x * MAXRD + tid] = ft | (lt << 8);
    }
}

// =============================================================================
// Kernel 3: selected affine apply -- zdup + 3-buffer ring, 2 blocks/SM.
// Grid (16 tiles, 16 oc-chunks of 32) x 256 thr.  Round = 32 items; thread =
// (item tid>>3, oct tid&7): 8 same-cell tokens x 4 outs in registers.
// z stored as u64 {z,z} in smem -> inner loop has ZERO dup movs:
// per r = 1 LDS.128 (w) + 8 LDS.64 (z) + 16 FFMA2  (fma-bound).
// Ring: stage tgs < min(ft+3, NTG); buf = tg % 3; wait_group = staged-lt-1.
// smem layout (bytes):
//   w ring : 0      .. 57024    (3 bufs x 4752 f32)
//   zdup   : 57024  .. 92928    (33 x 136 u64)
//   acc    : 92928  .. 111504   (129 x 36 f32)
//   rdesc  : 111504 .. 111584
// =============================================================================
#define SMEM_APPLY 111584

__global__ __launch_bounds__(256, 2) void kApply(
    const float* __restrict__ aw, const float* __restrict__ ab,
    float* __restrict__ out) {
    extern __shared__ __align__(16) unsigned char sm[];
    u64*   zdup    = (u64*)(sm + 57024);
    float* acc     = (float*)(sm + 92928);
    u32*   rdesc_s = (u32*)(sm + 111504);

    const int tid   = threadIdx.x;
    const int bx    = blockIdx.x;
    const int tile0 = bx * TILE_TOK;
    const int oc    = blockIdx.y * OC;
    const int oct   = tid & 7;
    const u32 smb   = (u32)__cvta_generic_to_shared(sm);
    const u32 zdupb = smb + 57024;
    const u32 accb  = smb + 92928;

    if (tid < 128) {   // stage zdup [r][tok] = {z,z}; bias row = 1; dummies 0
        const float4* zp = (const float4*)(g_z + (size_t)(tile0 + tid) * RANK);
#pragma unroll
        for (int j = 0; j < 8; j++) {
            const float4 v = zp[j];
            zdup[(4 * j + 0) * ZROW + tid] = dup2(v.x);
            zdup[(4 * j + 1) * ZROW + tid] = dup2(v.y);
            zdup[(4 * j + 2) * ZROW + tid] = dup2(v.z);
            zdup[(4 * j + 3) * ZROW + tid] = dup2(v.w);
        }
        zdup[32 * ZROW + tid] = dup2(1.0f);
        if (tid < 8)
#pragma unroll
            for (int r = 0; r < 33; r++) zdup[r * ZROW + 128 + tid] = 0ull;
    }
    for (int e = tid; e < 129 * ACCS; e += 256) acc[e] = 0.f;

    const int nit     = g_nit[bx];
    const int nrounds = nit >> 5;
    if (tid < nrounds) rdesc_s[tid] = g_rdesc[bx * MAXRD + tid];

    // prefetch round-0 item into registers
    u64 toks = __ldg(&g_itok[bx * MAXIT + (tid >> 3)]);
    u32 meta = __ldg(&g_imeta[bx * MAXIT + (tid >> 3)]);
    __syncthreads();

    int staged = 0;
    for (int rd = 0; rd < nrounds; rd++) {
        const u32 rdv = rdesc_s[rd];
        const int ft  = (int)(rdv & 0xFFu);
        const int lt  = (int)(rdv >> 8);
        int tgt = ft + 3; if (tgt > NTG) tgt = NTG;
        while (staged < tgt) {                            // stage tg 'staged'
            const int s = staged, b = s - (s / 3) * 3;    // s % 3
            for (int e = tid; e < 1056; e += 256) {       // 4 cells*33 r*8 f4
                const int c = e / 264, rem = e - c * 264;
                const int r = rem >> 3, j = rem & 7;
                const float* src = (r < 32)
                    ? aw + (((size_t)(s * 4 + c) * RANK + r) * OUT_DIM + oc + j * 4)
                    : ab + ((size_t)(s * 4 + c) * OUT_DIM + oc + j * 4);
                const u32 dst = smb +
                    (u32)((b * WBUF + c * WCELL + r * WROW + j * 4) * 4);
                asm volatile("cp.async.ca.shared.global [%0], [%1], 16;"
                             :: "r"(dst), "l"(src));
            }
            asm volatile("cp.async.commit_group;" ::: "memory");
            staged++;
        }
        {
            const int outst = staged - lt - 1;            // 0, 1 or 2
            if (outst >= 2)      asm volatile("cp.async.wait_group 2;" ::: "memory");
            else if (outst == 1) asm volatile("cp.async.wait_group 1;" ::: "memory");
            else                 asm volatile("cp.async.wait_group 0;" ::: "memory");
        }
        __syncthreads();

        // capture current item, prefetch next round's
        const u64 ctoks = toks;
        const u32 cmeta = meta;
        if (rd + 1 < nrounds) {
            toks = __ldg(&g_itok[bx * MAXIT + (rd + 1) * 32 + (tid >> 3)]);
            meta = __ldg(&g_imeta[bx * MAXIT + (rd + 1) * 32 + (tid >> 3)]);
        }

        const int cell = (int)(cmeta & 0xFFu);
        const int tg   = (int)(cmeta >> 8);
        const u32 wb   = smb +
            (u32)(((tg - (tg / 3) * 3) * WBUF + cell * WCELL) * 4) +
            (u32)(oct * 16);
        u32 zoff[8];
#pragma unroll
        for (int j = 0; j < 8; j++)
            zoff[j] = zdupb + (u32)(((ctoks >> (8 * j)) & 0xFF) * 8);

        u64 a[16];
#pragma unroll
        for (int i = 0; i < 16; i++) a[i] = 0ull;

#pragma unroll 3
        for (int r = 0; r < 33; r++) {
            u64 w0, w1;
            asm("ld.shared.v2.b64 {%0, %1}, [%2];"
                : "=l"(w0), "=l"(w1) : "r"(wb + (u32)(r * 144)));
#pragma unroll
            for (int j = 0; j < 8; j++) {
                u64 zd;
                asm("ld.shared.b64 %0, [%1];"
                    : "=l"(zd) : "r"(zoff[j] + (u32)(r * (ZROW * 8))));
                ffma2(a[2 * j],     zd, w0);
                ffma2(a[2 * j + 1], zd, w1);
            }
        }

        // ---- RMW acc in 3 static tg-mod-3 phases (span <= 3 adjacent tgs) ----
        const int myph = tg - (tg / 3) * 3;
#pragma unroll
        for (int ph = 0; ph < 3; ph++) {
            if (myph == ph) {
#pragma unroll
                for (int j = 0; j < 8; j++) {
                    const u32 p = (zoff[j] - zdupb) * (ACCS / 2) + accb +
                                  (u32)(oct * 16);
                    u64 c0, c1;
                    asm("ld.shared.v2.b64 {%0, %1}, [%2];"
                        : "=l"(c0), "=l"(c1) : "r"(p));
                    asm("add.rn.f32x2 %0, %0, %1;" : "+l"(c0) : "l"(a[2*j]));
                    asm("add.rn.f32x2 %0, %0, %1;" : "+l"(c1) : "l"(a[2*j+1]));
                    asm volatile("st.shared.v2.b64 [%0], {%1, %2};"
                                 :: "r"(p), "l"(c0), "l"(c1));
                }
            }
            __syncthreads();
        }
    }

    // ---- epilogue: scale + store (1024 float4 over 256 thr) ----
    const float S = 0.17677669529663687f;   // 1/sqrt(32)
    for (int e = tid; e < TILE_TOK * (OC / 4); e += 256) {
        const int tk = e >> 3, o4 = e & 7;
        float4 v = *(const float4*)(acc + tk * ACCS + o4 * 4);
        v.x *= S; v.y *= S; v.z *= S; v.w *= S;
        ((float4*)(out + (size_t)(tile0 + tk) * OUT_DIM + oc))[o4] = v;
    }
}

// =============================================================================
extern "C" void kernel_launch(void* const* d_in, const int* in_sizes, int n_in,
                              void* d_out, int out_size) {
    const float* x   = (const float*)d_in[0];
    const float* pw  = (const float*)d_in[1];
    const float* rw  = (const float*)d_in[2];
    const float* rb  = (const float*)d_in[3];
    const float* aw  = (const float*)d_in[4];
    const float* ab  = (const float*)d_in[5];
    float*       out = (float*)d_out;

    cudaFuncSetAttribute(kRoute, cudaFuncAttributeMaxDynamicSharedMemorySize,
                         SMEM_ROUTE);
    cudaFuncSetAttribute(kApply, cudaFuncAttributeMaxDynamicSharedMemorySize,
                         SMEM_APPLY);

    kInit<<<1, 32>>>();
    kRoute<<<TOKENS / 8, 256, SMEM_ROUTE>>>(x, pw, rw, rb);
    kSort<<<NTILE, 128>>>();
    kApply<<<dim3(NTILE, OUT_DIM / OC), 256, SMEM_APPLY>>>(aw, ab, out);
}

// round 11
// speedup vs baseline: 1.1074x; 1.1074x over previous
#include <cuda_runtime.h>
#include <cstdint>

typedef unsigned long long u64;
typedef unsigned int u32;

#define TOKENS   2048
#define IN_DIM   1024
#define OUT_DIM  512
#define RANK     32
#define NTG      32
#define NTILE    16
#define TILE_TOK 128
#define OC       32              // outputs per block
#define MAXIT    640
#define MAXRD    20
#define WROW     32              // floats per weight row (no pad)
#define WCELL    (33*WROW)       // 1056 floats per cell (32 w rows + bias row)
#define WBUF     (4*WCELL)       // 4224 floats per tg buffer (16896 B)
#define ZSTR     34              // zdup row stride in u64 (33 + 1 pad = 272 B)

// smem layout for kApply (bytes):
//   w ring : 0      .. 50688    (3 bufs x 4224 f32)
//   zdup   : 50688  .. 85776    (129 x 34 u64, token-major)
//   acc    : 85776  .. 102288   (129 x 32 f32)
//   rdesc  : 102288 .. 102368
#define SMEM_APPLY 102368

// ---------------- scratch (static device globals: allocation-free) ----------
__device__ __align__(16) float         g_z[TOKENS * RANK];
__device__ __align__(16) unsigned char g_win[TOKENS * NTG];
__device__ __align__(16) u64           g_itok[NTILE * MAXIT];
__device__ u32                         g_imeta[NTILE * MAXIT];
__device__ u32                         g_rdesc[NTILE * MAXRD];
__device__ int                         g_nit[NTILE];
__device__ int                         g_dummy;

// ---------------- helpers ----------------------------------------------------
__device__ __forceinline__ u64 dup2(float v) {
    u64 r; asm("mov.b64 %0, {%1, %1};" : "=l"(r) : "f"(v)); return r;
}
__device__ __forceinline__ void ffma2(u64& d, u64 a, u64 b) {
    asm("fma.rn.f32x2 %0, %1, %2, %0;" : "+l"(d) : "l"(a), "l"(b));
}

// =============================================================================
// Kernel 0: profiler-alignment dummy (ncu captures launch #4 = kApply).
// =============================================================================
__global__ void kInit() { if (threadIdx.x == 0) g_dummy = 1; }

// =============================================================================
// Kernel 1: z projection + routing argmin.  (verified 12.6us)
// =============================================================================
#define SMEM_ROUTE 50816

__global__ __launch_bounds__(256) void kRoute(
    const float* __restrict__ x, const float* __restrict__ proj_w,
    const float* __restrict__ router_w, const float* __restrict__ router_b) {
    extern __shared__ __align__(16) unsigned char smr[];
    float* xs   = (float*)smr;                       // [8][1024]
    float* rw_s = (float*)(smr + 32768);             // [32][129]
    float* rb_s = (float*)(smr + 49280);             // [128]
    float* zs   = (float*)(smr + 49792);             // [8][32]

    const int tid  = threadIdx.x;
    const int tok0 = blockIdx.x * 8;

    {   // stage 8 token rows of x (coalesced float4)
        const float4* xg  = (const float4*)(x + (size_t)tok0 * IN_DIM);
        float4*       xs4 = (float4*)xs;
#pragma unroll
        for (int i = 0; i < 8; i++) xs4[tid + 256 * i] = xg[tid + 256 * i];
    }
    {   // stage router_w coalesced -> padded rows (stride 129, bank-safe)
#pragma unroll
        for (int e = tid; e < 1024; e += 256) {
            const float4 v = ((const float4*)router_w)[e];
            const int tg = e >> 5, w4 = e & 31;
            float* d = &rw_s[tg * 129 + (w4 >> 3) * 32 + (w4 & 7) * 4];
            d[0] = v.x; d[1] = v.y; d[2] = v.z; d[3] = v.w;
        }
        if (tid < 128) rb_s[tid] = router_b[tid];
    }
    __syncthreads();

    const int w = tid >> 5, lane = tid & 31;
    float acc[4][8];
#pragma unroll
    for (int j = 0; j < 4; j++)
#pragma unroll
        for (int t = 0; t < 8; t++) acc[j][t] = 0.f;

    const float4* pw4 = (const float4*)(proj_w + (size_t)(w * 4) * IN_DIM) + lane;
    const float4* xs4 = (const float4*)xs + lane;

    float4 wv[4], wn[4];
#pragma unroll
    for (int j = 0; j < 4; j++) wv[j] = __ldg(pw4 + j * 256);

#pragma unroll
    for (int ci = 0; ci < 8; ci++) {
        if (ci < 7)
#pragma unroll
            for (int j = 0; j < 4; j++)
                wn[j] = __ldg(pw4 + j * 256 + (ci + 1) * 32);
#pragma unroll
        for (int t = 0; t < 8; t++) {
            const float4 xv = xs4[t * 256 + ci * 32];
#pragma unroll
            for (int j = 0; j < 4; j++) {
                acc[j][t] += wv[j].x * xv.x;
                acc[j][t] += wv[j].y * xv.y;
                acc[j][t] += wv[j].z * xv.z;
                acc[j][t] += wv[j].w * xv.w;
            }
        }
#pragma unroll
        for (int j = 0; j < 4; j++) wv[j] = wn[j];
    }

#pragma unroll
    for (int j = 0; j < 4; j++)
#pragma unroll
        for (int t = 0; t < 8; t++) {
            float s = acc[j][t];
#pragma unroll
            for (int off = 16; off > 0; off >>= 1)
                s += __shfl_xor_sync(0xffffffffu, s, off);
            if (lane == 0) zs[t * 32 + w * 4 + j] = s;
        }
    __syncthreads();

    if (tid < 64)
        ((float4*)(g_z + (size_t)tok0 * RANK))[tid] = ((const float4*)zs)[tid];

    {
        const int t  = tid >> 5;
        const int tg = tid & 31;
        float s[4];
#pragma unroll
        for (int k = 0; k < 4; k++) s[k] = rb_s[tg * 4 + k];
#pragma unroll 8
        for (int r = 0; r < RANK; r++) {
            const float zr = zs[t * 32 + r];
#pragma unroll
            for (int k = 0; k < 4; k++) s[k] += zr * rw_s[tg * 129 + k * 32 + r];
        }
        int best = 0; float bv = s[0];
#pragma unroll
        for (int k = 1; k < 4; k++)
            if (s[k] < bv) { bv = s[k]; best = k; }
        g_win[(size_t)(tok0 + t) * NTG + tg] = (unsigned char)best;
    }
}

// =============================================================================
// Kernel 2: per-tile cell sort -> flat item list (tg-ordered) + round descs.
// =============================================================================
__global__ __launch_bounds__(128) void kSort() {
    __shared__ unsigned char win_t[NTG][132];
    __shared__ unsigned char ord[NTG][160];
    __shared__ unsigned char offp[NTG][5];
    __shared__ int it_cnt[NTG];
    __shared__ int it_off[NTG + 1];
    __shared__ u64 s_itok[MAXIT];
    __shared__ u32 s_imeta[MAXIT];

    const int tid   = threadIdx.x;
    const int tile0 = blockIdx.x * TILE_TOK;

    {   // transpose win: [tok][tg] -> win_t[tg][tok]
        const u32* wp = (const u32*)(g_win + (size_t)(tile0 + tid) * NTG);
#pragma unroll
        for (int q = 0; q < 8; q++) {
            const u32 v = wp[q];
            win_t[q * 4 + 0][tid] = (unsigned char)(v);
            win_t[q * 4 + 1][tid] = (unsigned char)(v >> 8);
            win_t[q * 4 + 2][tid] = (unsigned char)(v >> 16);
            win_t[q * 4 + 3][tid] = (unsigned char)(v >> 24);
        }
    }
    __syncthreads();

    if (tid < NTG) {
        const int tg = tid;
        int cnt[4] = {0, 0, 0, 0};
        for (int t = 0; t < TILE_TOK; t++) cnt[win_t[tg][t]]++;
        int o[5]; o[0] = 0;
#pragma unroll
        for (int c = 0; c < 4; c++) o[c + 1] = o[c] + ((cnt[c] + 7) & ~7);
        int pos[4];
#pragma unroll
        for (int c = 0; c < 4; c++) pos[c] = o[c];
        for (int t = 0; t < TILE_TOK; t++) {
            const int c = win_t[tg][t];
            ord[tg][pos[c]++] = (unsigned char)t;
        }
#pragma unroll
        for (int c = 0; c < 4; c++)
            for (int i = cnt[c]; i < ((cnt[c] + 7) & ~7); i++)
                ord[tg][o[c] + i] = 128;               // dummy token
        it_cnt[tg] = o[4] >> 3;
#pragma unroll
        for (int c = 0; c < 5; c++) offp[tg][c] = (unsigned char)o[c];
    }
    __syncthreads();

    if (tid == 0) {
        int run = 0;
        for (int tg = 0; tg < NTG; tg++) { it_off[tg] = run; run += it_cnt[tg]; }
        it_off[NTG] = run;
    }
    __syncthreads();

    if (tid < NTG) {
        const int tg   = tid;
        const int base = it_off[tg];
        const int n    = it_cnt[tg];
        for (int i = 0; i < n; i++) {
            const int slot = i * 8;
            int cell = 3;
#pragma unroll
            for (int c = 0; c < 3; c++)
                if (slot < (int)offp[tg][c + 1]) { cell = c; break; }
            u64 tk = 0;
#pragma unroll
            for (int j = 0; j < 8; j++)
                tk |= (u64)ord[tg][slot + j] << (8 * j);
            s_itok[base + i]  = tk;
            s_imeta[base + i] = (u32)cell | ((u32)tg << 8);
        }
    }
    __syncthreads();

    const int total  = it_off[NTG];
    const int padded = (total + 31) & ~31;             // 32-item rounds
    if (tid == 0) g_nit[blockIdx.x] = padded;
    for (int e = total + tid; e < padded; e += 128) {
        s_itok[e]  = 0x8080808080808080ull;            // all-dummy item
        s_imeta[e] = (31u << 8);                       // tg 31, cell 0
    }
    __syncthreads();
    for (int e = tid; e < padded; e += 128) {
        g_itok[blockIdx.x * MAXIT + e]  = s_itok[e];
        g_imeta[blockIdx.x * MAXIT + e] = s_imeta[e];
    }
    const int nrounds = padded >> 5;
    if (tid < nrounds) {
        const u32 ft = s_imeta[tid * 32] >> 8;
        const u32 lt = s_imeta[tid * 32 + 31] >> 8;
        g_rdesc[blockIdx.x * MAXRD + tid] = ft | (lt << 8);
    }
}

// =============================================================================
// Kernel 3: selected affine apply -- token-major zdup, 2-r fused inner loop.
// Grid (16 tiles, 16 oc-chunks of 32) x 256 thr; 2 blocks/SM (102.4 KB smem).
// Thread = (item tid>>3, oct tid&7): 8 same-cell tokens x 4 outs in regs.
// zdup[tok][r] u64 {z,z}: one LDS.128 = z for TWO r-steps of one token ->
// per 2r: 8 z-loads + 2 w-loads + 32 FFMA2 (42 instr vs 64 fma-cyc).
// 3-buf ring (stage < ft+3), static mod-3 RMW phases.
// =============================================================================
__global__ __launch_bounds__(256, 2) void kApply(
    const float* __restrict__ aw, const float* __restrict__ ab,
    float* __restrict__ out) {
    extern __shared__ __align__(16) unsigned char sm[];
    u64*   zdup    = (u64*)(sm + 50688);   // [129][ZSTR]
    float* acc     = (float*)(sm + 85776); // [129][32]
    u32*   rdesc_s = (u32*)(sm + 102288);

    const int tid   = threadIdx.x;
    const int bx    = blockIdx.x;
    const int tile0 = bx * TILE_TOK;
    const int oc    = blockIdx.y * OC;
    const int oct   = tid & 7;
    const u32 smb   = (u32)__cvta_generic_to_shared(sm);
    const u32 zdupb = smb + 50688;
    const u32 accb  = smb + 85776;

    if (tid < 128) {   // zdup[tok][r] = {z,z}; r=32 bias partner = 1
        const float4* zp = (const float4*)(g_z + (size_t)(tile0 + tid) * RANK);
        u64* zr = zdup + tid * ZSTR;
#pragma unroll
        for (int j = 0; j < 8; j++) {
            const float4 v = zp[j];
            zr[4 * j + 0] = dup2(v.x);
            zr[4 * j + 1] = dup2(v.y);
            zr[4 * j + 2] = dup2(v.z);
            zr[4 * j + 3] = dup2(v.w);
        }
        zr[32] = dup2(1.0f);
        zr[33] = 0ull;
    }
    if (tid >= 128 && tid < 128 + ZSTR)                 // dummy token row = 0
        zdup[128 * ZSTR + (tid - 128)] = 0ull;
    for (int e = tid; e < 129 * 32; e += 256) acc[e] = 0.f;

    const int nit     = g_nit[bx];
    const int nrounds = nit >> 5;
    if (tid < nrounds) rdesc_s[tid] = g_rdesc[bx * MAXRD + tid];

    // prefetch round-0 item into registers
    u64 toks = __ldg(&g_itok[bx * MAXIT + (tid >> 3)]);
    u32 meta = __ldg(&g_imeta[bx * MAXIT + (tid >> 3)]);
    __syncthreads();

    int staged = 0;
    for (int rd = 0; rd < nrounds; rd++) {
        const u32 rdv = rdesc_s[rd];
        const int ft  = (int)(rdv & 0xFFu);
        const int lt  = (int)(rdv >> 8);
        int tgt = ft + 3; if (tgt > NTG) tgt = NTG;
        while (staged < tgt) {                            // stage tg 'staged'
            const int s = staged, b = s - (s / 3) * 3;    // s % 3
            for (int e = tid; e < 1056; e += 256) {       // 4 cells*33 r*8 f4
                const int c = e / 264, rem = e - c * 264;
                const int r = rem >> 3, j = rem & 7;
                const float* src = (r < 32)
                    ? aw + (((size_t)(s * 4 + c) * RANK + r) * OUT_DIM + oc + j * 4)
                    : ab + ((size_t)(s * 4 + c) * OUT_DIM + oc + j * 4);
                const u32 dst = smb +
                    (u32)((b * WBUF + c * WCELL + r * WROW + j * 4) * 4);
                asm volatile("cp.async.ca.shared.global [%0], [%1], 16;"
                             :: "r"(dst), "l"(src));
            }
            asm volatile("cp.async.commit_group;" ::: "memory");
            staged++;
        }
        {
            const int outst = staged - lt - 1;            // 0, 1 or 2
            if (outst >= 2)      asm volatile("cp.async.wait_group 2;" ::: "memory");
            else if (outst == 1) asm volatile("cp.async.wait_group 1;" ::: "memory");
            else                 asm volatile("cp.async.wait_group 0;" ::: "memory");
        }
        __syncthreads();

        // capture current item, prefetch next round's
        const u64 ctoks = toks;
        const u32 cmeta = meta;
        if (rd + 1 < nrounds) {
            toks = __ldg(&g_itok[bx * MAXIT + (rd + 1) * 32 + (tid >> 3)]);
            meta = __ldg(&g_imeta[bx * MAXIT + (rd + 1) * 32 + (tid >> 3)]);
        }

        const int cell = (int)(cmeta & 0xFFu);
        const int tg   = (int)(cmeta >> 8);
        const u32 wb   = smb +
            (u32)(((tg - (tg / 3) * 3) * WBUF + cell * WCELL) * 4) +
            (u32)(oct * 16);
        u32 zb[8];
#pragma unroll
        for (int j = 0; j < 8; j++)
            zb[j] = zdupb + (u32)(((ctoks >> (8 * j)) & 0xFF) * (ZSTR * 8));

        u64 a[16];
#pragma unroll
        for (int i = 0; i < 16; i++) a[i] = 0ull;

#pragma unroll 4
        for (int rp = 0; rp < 16; rp++) {                 // r = 2rp, 2rp+1
            u64 w0l, w0h, w1l, w1h;
            asm("ld.shared.v2.b64 {%0, %1}, [%2];"
                : "=l"(w0l), "=l"(w0h) : "r"(wb + (u32)(rp * 256)));
            asm("ld.shared.v2.b64 {%0, %1}, [%2];"
                : "=l"(w1l), "=l"(w1h) : "r"(wb + (u32)(rp * 256 + 128)));
#pragma unroll
            for (int j = 0; j < 8; j++) {
                u64 z0, z1;
                asm("ld.shared.v2.b64 {%0, %1}, [%2];"
                    : "=l"(z0), "=l"(z1) : "r"(zb[j] + (u32)(rp * 16)));
                ffma2(a[2 * j],     z0, w0l);
                ffma2(a[2 * j + 1], z0, w0h);
                ffma2(a[2 * j],     z1, w1l);
                ffma2(a[2 * j + 1], z1, w1h);
            }
        }
        {   // final r = 32 (bias row; z partner = 1)
            u64 wl, wh;
            asm("ld.shared.v2.b64 {%0, %1}, [%2];"
                : "=l"(wl), "=l"(wh) : "r"(wb + (u32)(32 * 128)));
#pragma unroll
            for (int j = 0; j < 8; j++) {
                u64 z0;
                asm("ld.shared.b64 %0, [%1];"
                    : "=l"(z0) : "r"(zb[j] + (u32)(32 * 8)));
                ffma2(a[2 * j],     z0, wl);
                ffma2(a[2 * j + 1], z0, wh);
            }
        }

        // ---- RMW acc in 3 static tg-mod-3 phases (span <= 3 adjacent tgs) ----
        const int myph = tg - (tg / 3) * 3;
#pragma unroll
        for (int ph = 0; ph < 3; ph++) {
            if (myph == ph) {
#pragma unroll
                for (int j = 0; j < 8; j++) {
                    const int tok = (int)((ctoks >> (8 * j)) & 0xFF);
                    const u32 p = accb + (u32)(tok * 128 + oct * 16);
                    u64 c0, c1;
                    asm("ld.shared.v2.b64 {%0, %1}, [%2];"
                        : "=l"(c0), "=l"(c1) : "r"(p));
                    asm("add.rn.f32x2 %0, %0, %1;" : "+l"(c0) : "l"(a[2*j]));
                    asm("add.rn.f32x2 %0, %0, %1;" : "+l"(c1) : "l"(a[2*j+1]));
                    asm volatile("st.shared.v2.b64 [%0], {%1, %2};"
                                 :: "r"(p), "l"(c0), "l"(c1));
                }
            }
            __syncthreads();
        }
    }

    // ---- epilogue: scale + store (1024 float4 over 256 thr) ----
    const float S = 0.17677669529663687f;   // 1/sqrt(32)
    for (int e = tid; e < TILE_TOK * (OC / 4); e += 256) {
        const int tk = e >> 3, o4 = e & 7;
        float4 v = *(const float4*)(acc + tk * 32 + o4 * 4);
        v.x *= S; v.y *= S; v.z *= S; v.w *= S;
        ((float4*)(out + (size_t)(tile0 + tk) * OUT_DIM + oc))[o4] = v;
    }
}

// =============================================================================
extern "C" void kernel_launch(void* const* d_in, const int* in_sizes, int n_in,
                              void* d_out, int out_size) {
    const float* x   = (const float*)d_in[0];
    const float* pw  = (const float*)d_in[1];
    const float* rw  = (const float*)d_in[2];
    const float* rb  = (const float*)d_in[3];
    const float* aw  = (const float*)d_in[4];
    const float* ab  = (const float*)d_in[5];
    float*       out = (float*)d_out;

    cudaFuncSetAttribute(kRoute, cudaFuncAttributeMaxDynamicSharedMemorySize,
                         SMEM_ROUTE);
    cudaFuncSetAttribute(kApply, cudaFuncAttributeMaxDynamicSharedMemorySize,
                         SMEM_APPLY);

    kInit<<<1, 32>>>();
    kRoute<<<TOKENS / 8, 256, SMEM_ROUTE>>>(x, pw, rw, rb);
    kSort<<<NTILE, 128>>>();
    kApply<<<dim3(NTILE, OUT_DIM / OC), 256, SMEM_APPLY>>>(aw, ab, out);
}

// round 12
// speedup vs baseline: 1.1159x; 1.0076x over previous
#include <cuda_runtime.h>
#include <cstdint>

typedef unsigned long long u64;
typedef unsigned int u32;

#define TOKENS   2048
#define IN_DIM   1024
#define OUT_DIM  512
#define RANK     32
#define NTG      32
#define NTILE    16
#define TILE_TOK 128
#define OC       32              // outputs per block
#define MAXIT    640
#define MAXRD    20
#define WROW     32              // floats per weight row (no pad)
#define WCELL    (33*WROW)       // 1056 floats per cell (32 w rows + bias row)
#define WBUF     (4*WCELL)       // 4224 floats per tg buffer (16896 B)
#define ZSTR     34              // zdup row stride in u64 (33 + 1 pad = 272 B)

// smem layout for kApply (bytes):
//   w ring : 0      .. 50688    (3 bufs x 4224 f32)
//   zdup   : 50688  .. 85776    (129 x 34 u64, token-major)
//   acc    : 85776  .. 102288   (129 x 32 f32)
//   rdesc  : 102288 .. 102368
#define SMEM_APPLY 102368

// ---------------- scratch (static device globals: allocation-free) ----------
__device__ __align__(16) float         g_z[TOKENS * RANK];
__device__ __align__(16) unsigned char g_win[TOKENS * NTG];
__device__ __align__(16) u64           g_itok[NTILE * MAXIT];
__device__ u32                         g_imeta[NTILE * MAXIT];
__device__ u32                         g_rdesc[NTILE * MAXRD];
__device__ int                         g_nit[NTILE];
__device__ int                         g_dummy;

// ---------------- helpers ----------------------------------------------------
__device__ __forceinline__ u64 dup2(float v) {
    u64 r; asm("mov.b64 %0, {%1, %1};" : "=l"(r) : "f"(v)); return r;
}
__device__ __forceinline__ void ffma2(u64& d, u64 a, u64 b) {
    asm("fma.rn.f32x2 %0, %1, %2, %0;" : "+l"(d) : "l"(a), "l"(b));
}

// =============================================================================
// Kernel 0: profiler-alignment dummy (ncu captures launch #4 = kApply).
// =============================================================================
__global__ void kInit() { if (threadIdx.x == 0) g_dummy = 1; }

// =============================================================================
// Kernel 1: z projection + routing argmin.  (verified 12.6us)
// =============================================================================
#define SMEM_ROUTE 50816

__global__ __launch_bounds__(256) void kRoute(
    const float* __restrict__ x, const float* __restrict__ proj_w,
    const float* __restrict__ router_w, const float* __restrict__ router_b) {
    extern __shared__ __align__(16) unsigned char smr[];
    float* xs   = (float*)smr;                       // [8][1024]
    float* rw_s = (float*)(smr + 32768);             // [32][129]
    float* rb_s = (float*)(smr + 49280);             // [128]
    float* zs   = (float*)(smr + 49792);             // [8][32]

    const int tid  = threadIdx.x;
    const int tok0 = blockIdx.x * 8;

    {   // stage 8 token rows of x (coalesced float4)
        const float4* xg  = (const float4*)(x + (size_t)tok0 * IN_DIM);
        float4*       xs4 = (float4*)xs;
#pragma unroll
        for (int i = 0; i < 8; i++) xs4[tid + 256 * i] = xg[tid + 256 * i];
    }
    {   // stage router_w coalesced -> padded rows (stride 129, bank-safe)
#pragma unroll
        for (int e = tid; e < 1024; e += 256) {
            const float4 v = ((const float4*)router_w)[e];
            const int tg = e >> 5, w4 = e & 31;
            float* d = &rw_s[tg * 129 + (w4 >> 3) * 32 + (w4 & 7) * 4];
            d[0] = v.x; d[1] = v.y; d[2] = v.z; d[3] = v.w;
        }
        if (tid < 128) rb_s[tid] = router_b[tid];
    }
    __syncthreads();

    const int w = tid >> 5, lane = tid & 31;
    float acc[4][8];
#pragma unroll
    for (int j = 0; j < 4; j++)
#pragma unroll
        for (int t = 0; t < 8; t++) acc[j][t] = 0.f;

    const float4* pw4 = (const float4*)(proj_w + (size_t)(w * 4) * IN_DIM) + lane;
    const float4* xs4 = (const float4*)xs + lane;

    float4 wv[4], wn[4];
#pragma unroll
    for (int j = 0; j < 4; j++) wv[j] = __ldg(pw4 + j * 256);

#pragma unroll
    for (int ci = 0; ci < 8; ci++) {
        if (ci < 7)
#pragma unroll
            for (int j = 0; j < 4; j++)
                wn[j] = __ldg(pw4 + j * 256 + (ci + 1) * 32);
#pragma unroll
        for (int t = 0; t < 8; t++) {
            const float4 xv = xs4[t * 256 + ci * 32];
#pragma unroll
            for (int j = 0; j < 4; j++) {
                acc[j][t] += wv[j].x * xv.x;
                acc[j][t] += wv[j].y * xv.y;
                acc[j][t] += wv[j].z * xv.z;
                acc[j][t] += wv[j].w * xv.w;
            }
        }
#pragma unroll
        for (int j = 0; j < 4; j++) wv[j] = wn[j];
    }

#pragma unroll
    for (int j = 0; j < 4; j++)
#pragma unroll
        for (int t = 0; t < 8; t++) {
            float s = acc[j][t];
#pragma unroll
            for (int off = 16; off > 0; off >>= 1)
                s += __shfl_xor_sync(0xffffffffu, s, off);
            if (lane == 0) zs[t * 32 + w * 4 + j] = s;
        }
    __syncthreads();

    if (tid < 64)
        ((float4*)(g_z + (size_t)tok0 * RANK))[tid] = ((const float4*)zs)[tid];

    {
        const int t  = tid >> 5;
        const int tg = tid & 31;
        float s[4];
#pragma unroll
        for (int k = 0; k < 4; k++) s[k] = rb_s[tg * 4 + k];
#pragma unroll 8
        for (int r = 0; r < RANK; r++) {
            const float zr = zs[t * 32 + r];
#pragma unroll
            for (int k = 0; k < 4; k++) s[k] += zr * rw_s[tg * 129 + k * 32 + r];
        }
        int best = 0; float bv = s[0];
#pragma unroll
        for (int k = 1; k < 4; k++)
            if (s[k] < bv) { bv = s[k]; best = k; }
        g_win[(size_t)(tok0 + t) * NTG + tg] = (unsigned char)best;
    }
}

// =============================================================================
// Kernel 2: per-tile cell sort -> flat item list (tg-ordered) + round descs.
// =============================================================================
__global__ __launch_bounds__(128) void kSort() {
    __shared__ unsigned char win_t[NTG][132];
    __shared__ unsigned char ord[NTG][160];
    __shared__ unsigned char offp[NTG][5];
    __shared__ int it_cnt[NTG];
    __shared__ int it_off[NTG + 1];
    __shared__ u64 s_itok[MAXIT];
    __shared__ u32 s_imeta[MAXIT];

    const int tid   = threadIdx.x;
    const int tile0 = blockIdx.x * TILE_TOK;

    {   // transpose win: [tok][tg] -> win_t[tg][tok]
        const u32* wp = (const u32*)(g_win + (size_t)(tile0 + tid) * NTG);
#pragma unroll
        for (int q = 0; q < 8; q++) {
            const u32 v = wp[q];
            win_t[q * 4 + 0][tid] = (unsigned char)(v);
            win_t[q * 4 + 1][tid] = (unsigned char)(v >> 8);
            win_t[q * 4 + 2][tid] = (unsigned char)(v >> 16);
            win_t[q * 4 + 3][tid] = (unsigned char)(v >> 24);
        }
    }
    __syncthreads();

    if (tid < NTG) {
        const int tg = tid;
        int cnt[4] = {0, 0, 0, 0};
        for (int t = 0; t < TILE_TOK; t++) cnt[win_t[tg][t]]++;
        int o[5]; o[0] = 0;
#pragma unroll
        for (int c = 0; c < 4; c++) o[c + 1] = o[c] + ((cnt[c] + 7) & ~7);
        int pos[4];
#pragma unroll
        for (int c = 0; c < 4; c++) pos[c] = o[c];
        for (int t = 0; t < TILE_TOK; t++) {
            const int c = win_t[tg][t];
            ord[tg][pos[c]++] = (unsigned char)t;
        }
#pragma unroll
        for (int c = 0; c < 4; c++)
            for (int i = cnt[c]; i < ((cnt[c] + 7) & ~7); i++)
                ord[tg][o[c] + i] = 128;               // dummy token
        it_cnt[tg] = o[4] >> 3;
#pragma unroll
        for (int c = 0; c < 5; c++) offp[tg][c] = (unsigned char)o[c];
    }
    __syncthreads();

    if (tid == 0) {
        int run = 0;
        for (int tg = 0; tg < NTG; tg++) { it_off[tg] = run; run += it_cnt[tg]; }
        it_off[NTG] = run;
    }
    __syncthreads();

    if (tid < NTG) {
        const int tg   = tid;
        const int base = it_off[tg];
        const int n    = it_cnt[tg];
        for (int i = 0; i < n; i++) {
            const int slot = i * 8;
            int cell = 3;
#pragma unroll
            for (int c = 0; c < 3; c++)
                if (slot < (int)offp[tg][c + 1]) { cell = c; break; }
            u64 tk = 0;
#pragma unroll
            for (int j = 0; j < 8; j++)
                tk |= (u64)ord[tg][slot + j] << (8 * j);
            s_itok[base + i]  = tk;
            s_imeta[base + i] = (u32)cell | ((u32)tg << 8);
        }
    }
    __syncthreads();

    const int total  = it_off[NTG];
    const int padded = (total + 31) & ~31;             // 32-item rounds
    if (tid == 0) g_nit[blockIdx.x] = padded;
    for (int e = total + tid; e < padded; e += 128) {
        s_itok[e]  = 0x8080808080808080ull;            // all-dummy item
        s_imeta[e] = (31u << 8);                       // tg 31, cell 0
    }
    __syncthreads();
    for (int e = tid; e < padded; e += 128) {
        g_itok[blockIdx.x * MAXIT + e]  = s_itok[e];
        g_imeta[blockIdx.x * MAXIT + e] = s_imeta[e];
    }
    const int nrounds = padded >> 5;
    if (tid < nrounds) {
        const u32 ft = s_imeta[tid * 32] >> 8;
        const u32 lt = s_imeta[tid * 32 + 31] >> 8;
        g_rdesc[blockIdx.x * MAXRD + tid] = ft | (lt << 8);
    }
}

// =============================================================================
// Kernel 3: selected affine apply -- token-major zdup, 2-r fused inner loop.
// Grid (16 tiles, 16 oc-chunks of 32) x 256 thr; 2 blocks/SM (102.4 KB smem).
// Thread = (item tid>>3, oct tid&7): 8 same-cell tokens x 4 outs in regs.
// zdup[tok][r] u64 {z,z}: one LDS.128 = z for TWO r-steps of one token ->
// per 2r: 8 z-loads + 2 w-loads + 32 FFMA2 (42 instr vs 64 fma-cyc).
// 3-buf ring (stage < ft+3), static mod-3 RMW phases.
// =============================================================================
__global__ __launch_bounds__(256, 2) void kApply(
    const float* __restrict__ aw, const float* __restrict__ ab,
    float* __restrict__ out) {
    extern __shared__ __align__(16) unsigned char sm[];
    u64*   zdup    = (u64*)(sm + 50688);   // [129][ZSTR]
    float* acc     = (float*)(sm + 85776); // [129][32]
    u32*   rdesc_s = (u32*)(sm + 102288);

    const int tid   = threadIdx.x;
    const int bx    = blockIdx.x;
    const int tile0 = bx * TILE_TOK;
    const int oc    = blockIdx.y * OC;
    const int oct   = tid & 7;
    const u32 smb   = (u32)__cvta_generic_to_shared(sm);
    const u32 zdupb = smb + 50688;
    const u32 accb  = smb + 85776;

    if (tid < 128) {   // zdup[tok][r] = {z,z}; r=32 bias partner = 1
        const float4* zp = (const float4*)(g_z + (size_t)(tile0 + tid) * RANK);
        u64* zr = zdup + tid * ZSTR;
#pragma unroll
        for (int j = 0; j < 8; j++) {
            const float4 v = zp[j];
            zr[4 * j + 0] = dup2(v.x);
            zr[4 * j + 1] = dup2(v.y);
            zr[4 * j + 2] = dup2(v.z);
            zr[4 * j + 3] = dup2(v.w);
        }
        zr[32] = dup2(1.0f);
        zr[33] = 0ull;
    }
    if (tid >= 128 && tid < 128 + ZSTR)                 // dummy token row = 0
        zdup[128 * ZSTR + (tid - 128)] = 0ull;
    for (int e = tid; e < 129 * 32; e += 256) acc[e] = 0.f;

    const int nit     = g_nit[bx];
    const int nrounds = nit >> 5;
    if (tid < nrounds) rdesc_s[tid] = g_rdesc[bx * MAXRD + tid];

    // prefetch round-0 item into registers
    u64 toks = __ldg(&g_itok[bx * MAXIT + (tid >> 3)]);
    u32 meta = __ldg(&g_imeta[bx * MAXIT + (tid >> 3)]);
    __syncthreads();

    int staged = 0;
    for (int rd = 0; rd < nrounds; rd++) {
        const u32 rdv = rdesc_s[rd];
        const int ft  = (int)(rdv & 0xFFu);
        const int lt  = (int)(rdv >> 8);
        int tgt = ft + 3; if (tgt > NTG) tgt = NTG;
        while (staged < tgt) {                            // stage tg 'staged'
            const int s = staged, b = s - (s / 3) * 3;    // s % 3
            for (int e = tid; e < 1056; e += 256) {       // 4 cells*33 r*8 f4
                const int c = e / 264, rem = e - c * 264;
                const int r = rem >> 3, j = rem & 7;
                const float* src = (r < 32)
                    ? aw + (((size_t)(s * 4 + c) * RANK + r) * OUT_DIM + oc + j * 4)
                    : ab + ((size_t)(s * 4 + c) * OUT_DIM + oc + j * 4);
                const u32 dst = smb +
                    (u32)((b * WBUF + c * WCELL + r * WROW + j * 4) * 4);
                asm volatile("cp.async.ca.shared.global [%0], [%1], 16;"
                             :: "r"(dst), "l"(src));
            }
            asm volatile("cp.async.commit_group;" ::: "memory");
            staged++;
        }
        {
            const int outst = staged - lt - 1;            // 0, 1 or 2
            if (outst >= 2)      asm volatile("cp.async.wait_group 2;" ::: "memory");
            else if (outst == 1) asm volatile("cp.async.wait_group 1;" ::: "memory");
            else                 asm volatile("cp.async.wait_group 0;" ::: "memory");
        }
        __syncthreads();

        // capture current item, prefetch next round's
        const u64 ctoks = toks;
        const u32 cmeta = meta;
        if (rd + 1 < nrounds) {
            toks = __ldg(&g_itok[bx * MAXIT + (rd + 1) * 32 + (tid >> 3)]);
            meta = __ldg(&g_imeta[bx * MAXIT + (rd + 1) * 32 + (tid >> 3)]);
        }

        const int cell = (int)(cmeta & 0xFFu);
        const int tg   = (int)(cmeta >> 8);
        const u32 wb   = smb +
            (u32)(((tg - (tg / 3) * 3) * WBUF + cell * WCELL) * 4) +
            (u32)(oct * 16);
        u32 zb[8];
#pragma unroll
        for (int j = 0; j < 8; j++)
            zb[j] = zdupb + (u32)(((ctoks >> (8 * j)) & 0xFF) * (ZSTR * 8));

        u64 a[16];
#pragma unroll
        for (int i = 0; i < 16; i++) a[i] = 0ull;

#pragma unroll 4
        for (int rp = 0; rp < 16; rp++) {                 // r = 2rp, 2rp+1
            u64 w0l, w0h, w1l, w1h;
            asm("ld.shared.v2.b64 {%0, %1}, [%2];"
                : "=l"(w0l), "=l"(w0h) : "r"(wb + (u32)(rp * 256)));
            asm("ld.shared.v2.b64 {%0, %1}, [%2];"
                : "=l"(w1l), "=l"(w1h) : "r"(wb + (u32)(rp * 256 + 128)));
#pragma unroll
            for (int j = 0; j < 8; j++) {
                u64 z0, z1;
                asm("ld.shared.v2.b64 {%0, %1}, [%2];"
                    : "=l"(z0), "=l"(z1) : "r"(zb[j] + (u32)(rp * 16)));
                ffma2(a[2 * j],     z0, w0l);
                ffma2(a[2 * j + 1], z0, w0h);
                ffma2(a[2 * j],     z1, w1l);
                ffma2(a[2 * j + 1], z1, w1h);
            }
        }
        {   // final r = 32 (bias row; z partner = 1)
            u64 wl, wh;
            asm("ld.shared.v2.b64 {%0, %1}, [%2];"
                : "=l"(wl), "=l"(wh) : "r"(wb + (u32)(32 * 128)));
#pragma unroll
            for (int j = 0; j < 8; j++) {
                u64 z0;
                asm("ld.shared.b64 %0, [%1];"
                    : "=l"(z0) : "r"(zb[j] + (u32)(32 * 8)));
                ffma2(a[2 * j],     z0, wl);
                ffma2(a[2 * j + 1], z0, wh);
            }
        }

        // ---- RMW acc in 3 static tg-mod-3 phases (span <= 3 adjacent tgs) ----
        const int myph = tg - (tg / 3) * 3;
#pragma unroll
        for (int ph = 0; ph < 3; ph++) {
            if (myph == ph) {
#pragma unroll
                for (int j = 0; j < 8; j++) {
                    const int tok = (int)((ctoks >> (8 * j)) & 0xFF);
                    const u32 p = accb + (u32)(tok * 128 + oct * 16);
                    u64 c0, c1;
                    asm("ld.shared.v2.b64 {%0, %1}, [%2];"
                        : "=l"(c0), "=l"(c1) : "r"(p));
                    asm("add.rn.f32x2 %0, %0, %1;" : "+l"(c0) : "l"(a[2*j]));
                    asm("add.rn.f32x2 %0, %0, %1;" : "+l"(c1) : "l"(a[2*j+1]));
                    asm volatile("st.shared.v2.b64 [%0], {%1, %2};"
                                 :: "r"(p), "l"(c0), "l"(c1));
                }
            }
            __syncthreads();
        }
    }

    // ---- epilogue: scale + store (1024 float4 over 256 thr) ----
    const float S = 0.17677669529663687f;   // 1/sqrt(32)
    for (int e = tid; e < TILE_TOK * (OC / 4); e += 256) {
        const int tk = e >> 3, o4 = e & 7;
        float4 v = *(const float4*)(acc + tk * 32 + o4 * 4);
        v.x *= S; v.y *= S; v.z *= S; v.w *= S;
        ((float4*)(out + (size_t)(tile0 + tk) * OUT_DIM + oc))[o4] = v;
    }
}

// =============================================================================
extern "C" void kernel_launch(void* const* d_in, const int* in_sizes, int n_in,
                              void* d_out, int out_size) {
    const float* x   = (const float*)d_in[0];
    const float* pw  = (const float*)d_in[1];
    const float* rw  = (const float*)d_in[2];
    const float* rb  = (const float*)d_in[3];
    const float* aw  = (const float*)d_in[4];
    const float* ab  = (const float*)d_in[5];
    float*       out = (float*)d_out;

    cudaFuncSetAttribute(kRoute, cudaFuncAttributeMaxDynamicSharedMemorySize,
                         SMEM_ROUTE);
    cudaFuncSetAttribute(kApply, cudaFuncAttributeMaxDynamicSharedMemorySize,
                         SMEM_APPLY);

    kInit<<<1, 32>>>();
    kRoute<<<TOKENS / 8, 256, SMEM_ROUTE>>>(x, pw, rw, rb);
    kSort<<<NTILE, 128>>>();
    kApply<<<dim3(NTILE, OUT_DIM / OC), 256, SMEM_APPLY>>>(aw, ab, out);
}